// round 4
// baseline (speedup 1.0000x reference)
#include <cuda_runtime.h>
#include <cuda_bf16.h>
#include <math.h>
#include <cstdint>

// Problem constants
#define BB   2
#define KK   8
#define CC   256
#define HW   16384
#define SS   2048
#define SIM_TH 0.95f
#define EPS_DEN 1e-6f
#define EPS_NRM 1e-12f

// Gram tiling
#define TM 128
#define TN 128
#define KC 64                         // bf16 channels per stage
#define NT (SS / TM)                  // 16
#define NPAIR ((NT * (NT + 1)) / 2)   // 136
#define SROW 72                       // padded smem row (bf16): conflict-free ldmatrix

// Scratch (no allocation allowed)
__device__ __align__(16) __nv_bfloat16 g_fh[BB][SS][CC];
__device__ float g_m[BB][KK][SS];
__device__ float g_num;
__device__ float g_den;

// cp.async helpers
#define CP_ASYNC16(dst_smem_u32, src_gptr) \
    asm volatile("cp.async.cg.shared.global [%0], [%1], 16;" \
                 :: "r"(dst_smem_u32), "l"(src_gptr))
#define CP_COMMIT() asm volatile("cp.async.commit_group;" ::: "memory")
#define CP_WAIT0()  asm volatile("cp.async.wait_group 0;" ::: "memory")
#define CP_WAIT1()  asm volatile("cp.async.wait_group 1;" ::: "memory")

// ---------------------------------------------------------------------------
// Kernel 1: gather + normalize features (2 warps per sample, bf16 out),
//           mask sigmoid gather, zero accumulators.
// grid: 1024 x 256  (8192 warps = 2 * B*S)
// ---------------------------------------------------------------------------
__global__ void gather_kernel(const float* __restrict__ masks,
                              const float* __restrict__ feats,
                              const int*   __restrict__ indices)
{
    __shared__ float s_ss[8];

    const int tid  = threadIdx.x;
    const int wid  = tid >> 5;
    const int lane = tid & 31;
    const int gtid = blockIdx.x * blockDim.x + tid;

    if (gtid == 0) { g_num = 0.0f; g_den = 0.0f; }

    // mask gather: 32768 entries, 32 per block
    if (tid < 32) {
        int e = blockIdx.x * 32 + tid;
        int b = e / (KK * SS);
        int r = e % (KK * SS);
        int k = r / SS;
        int s = r % SS;
        int hw = indices[b * SS + s];
        float x = masks[(b * KK + k) * HW + hw];
        g_m[b][k][s] = 1.0f / (1.0f + expf(-x));
    }

    // features: warp pair per sample; each warp handles 128 channels (4/lane)
    const int gwarp  = blockIdx.x * 8 + wid;      // 0..8191
    const int sample = gwarp >> 1;                // 0..4095
    const int half   = gwarp & 1;
    const int b = sample / SS;
    const int s = sample % SS;
    const int hw = indices[b * SS + s];
    const int cbase = half * 128;

    float v[4];
    float ss = 0.0f;
#pragma unroll
    for (int u = 0; u < 4; u++) {
        int c = cbase + u * 32 + lane;
        float x = feats[((size_t)(b * CC + c)) * HW + hw];
        v[u] = x;
        ss += x * x;
    }
#pragma unroll
    for (int off = 16; off > 0; off >>= 1)
        ss += __shfl_xor_sync(0xFFFFFFFFu, ss, off);

    if (lane == 0) s_ss[wid] = ss;
    __syncthreads();
    float tot = s_ss[wid & ~1] + s_ss[wid | 1];

    float inv = 1.0f / fmaxf(sqrtf(tot), EPS_NRM);
#pragma unroll
    for (int u = 0; u < 4; u++) {
        int c = cbase + u * 32 + lane;
        g_fh[b][s][c] = __float2bfloat16(v[u] * inv);
    }
}

// ---------------------------------------------------------------------------
// Kernel 2: bf16 mma.sync Gram, cp.async double-buffered staging + fused
// affinity. 256 threads (8 warps, 2x4 warp grid, warp tile 64x32).
// Dynamic smem: As[2][128][72] | Bs[2][128][72] | Ms[8][128] | Mt[8][128] | red[16]
// ---------------------------------------------------------------------------
#define STAGE_ELEMS (TM * SROW)                    // bf16 per matrix per stage
#define SMEM_AB     (2 * 2 * STAGE_ELEMS)          // total bf16 for As+Bs
#define SMEM_BYTES  (SMEM_AB * 2 + (2 * KK * 128 + 16) * 4)

__global__ __launch_bounds__(256)
void gram_affinity_kernel()
{
    extern __shared__ __align__(16) char dyn[];
    __nv_bfloat16* As = (__nv_bfloat16*)dyn;                    // [2][128][72]
    __nv_bfloat16* Bs = As + 2 * STAGE_ELEMS;                   // [2][128][72]
    float* Ms  = (float*)(dyn + SMEM_AB * 2);                   // [8][128]
    float* Mt  = Ms + KK * 128;                                 // [8][128]
    float* red = Mt + KK * 128;                                 // [16]

    const int tid = threadIdx.x;
    const int b = blockIdx.x / NPAIR;
    int p = blockIdx.x % NPAIR;

    int j = 0;
    while (((j + 1) * (j + 2)) / 2 <= p) j++;
    int i = p - (j * (j + 1)) / 2;

    const int s0 = i * TM;
    const int t0 = j * TN;
    const float w = (i == j) ? 1.0f : 2.0f;

    const int lane = tid & 31;
    const int wid  = tid >> 5;
    const int wm   = wid & 1;       // 0..1 (64 rows)
    const int wn   = wid >> 1;      // 0..3 (32 cols)

    // staging indices: idx = tid + it*256, row = idx>>3, 16B chunk = idx&7
    const int lrow = tid >> 3;           // base row for it=0 (rows 0..31)
    const int lch  = (tid & 7) * 8;      // bf16 col within row

    const uint32_t as_base = (uint32_t)__cvta_generic_to_shared(As);
    const uint32_t bs_base = (uint32_t)__cvta_generic_to_shared(Bs);

    // issue stage 0 (kc = 0)
#pragma unroll
    for (int it = 0; it < 4; it++) {
        int row = lrow + it * 32;
        uint32_t soff = (uint32_t)(row * SROW + lch) * 2;
        CP_ASYNC16(as_base + soff, &g_fh[b][s0 + row][lch]);
        CP_ASYNC16(bs_base + soff, &g_fh[b][t0 + row][lch]);
    }
    CP_COMMIT();

    // m tiles while stage 0 is in flight
#pragma unroll
    for (int it = 0; it < 4; it++) {
        int q = tid + it * 256;
        int k = q >> 7;
        int r = q & 127;
        Ms[k * 128 + r] = g_m[b][k][s0 + r];
        Mt[k * 128 + r] = g_m[b][k][t0 + r];
    }

    float acc[4][4][4];
#pragma unroll
    for (int im = 0; im < 4; im++)
#pragma unroll
        for (int in = 0; in < 4; in++)
#pragma unroll
            for (int r = 0; r < 4; r++) acc[im][in][r] = 0.0f;

    // ldmatrix lane addressing (same as proven R2 kernel)
    const int a_r   = lane & 15;
    const int a_sel = (lane >> 4) << 3;
    const int b_r   = (lane & 7) + ((lane >> 4) << 3);
    const int b_sel = ((lane >> 3) & 1) << 3;

    for (int ck = 0; ck < 4; ck++) {
        // prefetch next stage
        if (ck < 3) {
            const int kcn = (ck + 1) * KC;
            const int stn = (ck + 1) & 1;
#pragma unroll
            for (int it = 0; it < 4; it++) {
                int row = lrow + it * 32;
                uint32_t soff = (uint32_t)(stn * STAGE_ELEMS + row * SROW + lch) * 2;
                CP_ASYNC16(as_base + soff, &g_fh[b][s0 + row][kcn + lch]);
                CP_ASYNC16(bs_base + soff, &g_fh[b][t0 + row][kcn + lch]);
            }
            CP_COMMIT();
            CP_WAIT1();
        } else {
            CP_WAIT0();
        }
        __syncthreads();

        const int st = ck & 1;
        __nv_bfloat16* Ac = As + st * STAGE_ELEMS;
        __nv_bfloat16* Bc = Bs + st * STAGE_ELEMS;

#pragma unroll
        for (int kk = 0; kk < KC; kk += 16) {
            unsigned af[4][4];
#pragma unroll
            for (int im = 0; im < 4; im++) {
                unsigned addr = (unsigned)__cvta_generic_to_shared(
                    &Ac[(wm * 64 + im * 16 + a_r) * SROW + kk + a_sel]);
                asm volatile(
                    "ldmatrix.sync.aligned.m8n8.x4.shared.b16 {%0,%1,%2,%3}, [%4];"
                    : "=r"(af[im][0]), "=r"(af[im][1]), "=r"(af[im][2]), "=r"(af[im][3])
                    : "r"(addr));
            }
            unsigned bq[2][4];
#pragma unroll
            for (int q = 0; q < 2; q++) {
                unsigned addr = (unsigned)__cvta_generic_to_shared(
                    &Bc[(wn * 32 + q * 16 + b_r) * SROW + kk + b_sel]);
                asm volatile(
                    "ldmatrix.sync.aligned.m8n8.x4.shared.b16 {%0,%1,%2,%3}, [%4];"
                    : "=r"(bq[q][0]), "=r"(bq[q][1]), "=r"(bq[q][2]), "=r"(bq[q][3])
                    : "r"(addr));
            }
#pragma unroll
            for (int im = 0; im < 4; im++) {
#pragma unroll
                for (int in = 0; in < 4; in++) {
                    unsigned b0 = bq[in >> 1][(in & 1) * 2];
                    unsigned b1 = bq[in >> 1][(in & 1) * 2 + 1];
                    asm volatile(
                        "mma.sync.aligned.m16n8k16.row.col.f32.bf16.bf16.f32 "
                        "{%0,%1,%2,%3}, {%4,%5,%6,%7}, {%8,%9}, {%0,%1,%2,%3};"
                        : "+f"(acc[im][in][0]), "+f"(acc[im][in][1]),
                          "+f"(acc[im][in][2]), "+f"(acc[im][in][3])
                        : "r"(af[im][0]), "r"(af[im][1]), "r"(af[im][2]), "r"(af[im][3]),
                          "r"(b0), "r"(b1));
                }
            }
        }
        __syncthreads();
    }

    // fused affinity epilogue (threshold branch rarely taken)
    const int gr = lane >> 2;
    const int gc = (lane & 3) * 2;
    float numL = 0.0f, denL = 0.0f;
#pragma unroll
    for (int im = 0; im < 4; im++) {
#pragma unroll
        for (int in = 0; in < 4; in++) {
#pragma unroll
            for (int r = 0; r < 4; r++) {
                if (acc[im][in][r] > SIM_TH) {
                    int row = wm * 64 + im * 16 + gr + ((r >> 1) << 3);
                    int col = wn * 32 + in * 8 + gc + (r & 1);
                    denL += 1.0f;
                    float d = 0.0f;
#pragma unroll
                    for (int k = 0; k < KK; k++)
                        d += fabsf(Ms[k * 128 + row] - Mt[k * 128 + col]);
                    numL += d;
                }
            }
        }
    }
    numL *= w;
    denL *= w;

#pragma unroll
    for (int off = 16; off > 0; off >>= 1) {
        numL += __shfl_xor_sync(0xFFFFFFFFu, numL, off);
        denL += __shfl_xor_sync(0xFFFFFFFFu, denL, off);
    }
    if (lane == 0) { red[wid] = numL; red[8 + wid] = denL; }
    __syncthreads();
    if (tid == 0) {
        float n = 0.0f, d = 0.0f;
#pragma unroll
        for (int q = 0; q < 8; q++) { n += red[q]; d += red[8 + q]; }
        atomicAdd(&g_num, n);
        atomicAdd(&g_den, d);
    }
}

// ---------------------------------------------------------------------------
__global__ void finalize_kernel(float* out)
{
    out[0] = g_num / (g_den + EPS_DEN);
}

extern "C" void kernel_launch(void* const* d_in, const int* in_sizes, int n_in,
                              void* d_out, int out_size)
{
    const float* masks   = (const float*)d_in[0];
    const float* feats   = (const float*)d_in[1];
    const int*   indices = (const int*)d_in[2];
    float* out = (float*)d_out;

    cudaFuncSetAttribute(gram_affinity_kernel,
                         cudaFuncAttributeMaxDynamicSharedMemorySize, SMEM_BYTES);

    gather_kernel<<<1024, 256>>>(masks, feats, indices);
    gram_affinity_kernel<<<BB * NPAIR, 256, SMEM_BYTES>>>();
    finalize_kernel<<<1, 1>>>(out);
}

// round 5
// speedup vs baseline: 1.0013x; 1.0013x over previous
#include <cuda_runtime.h>
#include <cuda_fp16.h>
#include <math.h>
#include <cstdint>

// Problem constants
#define BB   2
#define KK   8
#define CC   256
#define HW   16384
#define SS   2048
#define SIM_TH 0.95f
#define EPS_DEN 1e-6f
#define EPS_NRM 1e-12f

// Gram tiling
#define TM 128
#define TN 128
#define KC 64                         // f16 channels per stage
#define NT (SS / TM)                  // 16
#define NPAIR ((NT * (NT + 1)) / 2)   // 136
#define GRID2 (BB * NPAIR)            // 272
#define SROW 72                       // padded smem row (f16)

// Scratch (no allocation allowed)
__device__ __align__(16) __half g_fh[BB][SS][CC];
__device__ float g_m[BB][KK][SS];
__device__ float g_num;
__device__ float g_den;
__device__ unsigned g_done;

// cp.async helpers
#define CP_ASYNC16(dst_smem_u32, src_gptr) \
    asm volatile("cp.async.cg.shared.global [%0], [%1], 16;" \
                 :: "r"(dst_smem_u32), "l"(src_gptr))
#define CP_COMMIT() asm volatile("cp.async.commit_group;" ::: "memory")
#define CP_WAIT0()  asm volatile("cp.async.wait_group 0;" ::: "memory")
#define CP_WAIT1()  asm volatile("cp.async.wait_group 1;" ::: "memory")

// ---------------------------------------------------------------------------
// Kernel 1: gather + normalize features (2 warps per sample, f16 out),
//           mask sigmoid gather, zero accumulators + completion counter.
// ---------------------------------------------------------------------------
__global__ void gather_kernel(const float* __restrict__ masks,
                              const float* __restrict__ feats,
                              const int*   __restrict__ indices)
{
    __shared__ float s_ss[8];

    const int tid  = threadIdx.x;
    const int wid  = tid >> 5;
    const int lane = tid & 31;
    const int gtid = blockIdx.x * blockDim.x + tid;

    if (gtid == 0) { g_num = 0.0f; g_den = 0.0f; g_done = 0u; }

    // mask gather: 32768 entries, 32 per block
    if (tid < 32) {
        int e = blockIdx.x * 32 + tid;
        int b = e / (KK * SS);
        int r = e % (KK * SS);
        int k = r / SS;
        int s = r % SS;
        int hw = indices[b * SS + s];
        float x = masks[(b * KK + k) * HW + hw];
        g_m[b][k][s] = 1.0f / (1.0f + expf(-x));
    }

    // features: warp pair per sample; each warp handles 128 channels
    const int gwarp  = blockIdx.x * 8 + wid;
    const int sample = gwarp >> 1;
    const int half   = gwarp & 1;
    const int b = sample / SS;
    const int s = sample % SS;
    const int hw = indices[b * SS + s];
    const int cbase = half * 128;

    float v[4];
    float ss = 0.0f;
#pragma unroll
    for (int u = 0; u < 4; u++) {
        int c = cbase + u * 32 + lane;
        float x = feats[((size_t)(b * CC + c)) * HW + hw];
        v[u] = x;
        ss += x * x;
    }
#pragma unroll
    for (int off = 16; off > 0; off >>= 1)
        ss += __shfl_xor_sync(0xFFFFFFFFu, ss, off);

    if (lane == 0) s_ss[wid] = ss;
    __syncthreads();
    float tot = s_ss[wid & ~1] + s_ss[wid | 1];

    float inv = 1.0f / fmaxf(sqrtf(tot), EPS_NRM);
#pragma unroll
    for (int u = 0; u < 4; u++) {
        int c = cbase + u * 32 + lane;
        g_fh[b][s][c] = __float2half(v[u] * inv);
    }
}

// ---------------------------------------------------------------------------
// Kernel 2: f16 mma.sync (fp16 accumulators) Gram + fused affinity + final.
// 256 threads, 8 warps (2x4), warp tile 64x32, cp.async double-buffered.
// ---------------------------------------------------------------------------
#define STAGE_ELEMS (TM * SROW)
#define SMEM_AB     (2 * 2 * STAGE_ELEMS)
#define SMEM_BYTES  (SMEM_AB * 2 + (2 * KK * 128 + 16) * 4)

__global__ __launch_bounds__(256)
void gram_affinity_kernel(float* __restrict__ out)
{
    extern __shared__ __align__(16) char dyn[];
    __half* As = (__half*)dyn;                       // [2][128][72]
    __half* Bs = As + 2 * STAGE_ELEMS;               // [2][128][72]
    float* Ms  = (float*)(dyn + SMEM_AB * 2);        // [8][128]
    float* Mt  = Ms + KK * 128;                      // [8][128]
    float* red = Mt + KK * 128;                      // [16]

    const int tid = threadIdx.x;
    const int b = blockIdx.x / NPAIR;
    int p = blockIdx.x % NPAIR;

    int j = 0;
    while (((j + 1) * (j + 2)) / 2 <= p) j++;
    int i = p - (j * (j + 1)) / 2;

    const int s0 = i * TM;
    const int t0 = j * TN;
    const float w = (i == j) ? 1.0f : 2.0f;

    const int lane = tid & 31;
    const int wid  = tid >> 5;
    const int wm   = wid & 1;
    const int wn   = wid >> 1;

    const int lrow = tid >> 3;
    const int lch  = (tid & 7) * 8;

    const uint32_t as_base = (uint32_t)__cvta_generic_to_shared(As);
    const uint32_t bs_base = (uint32_t)__cvta_generic_to_shared(Bs);

    // stage 0
#pragma unroll
    for (int it = 0; it < 4; it++) {
        int row = lrow + it * 32;
        uint32_t soff = (uint32_t)(row * SROW + lch) * 2;
        CP_ASYNC16(as_base + soff, &g_fh[b][s0 + row][lch]);
        CP_ASYNC16(bs_base + soff, &g_fh[b][t0 + row][lch]);
    }
    CP_COMMIT();

    // m tiles while stage 0 is in flight
#pragma unroll
    for (int it = 0; it < 4; it++) {
        int q = tid + it * 256;
        int k = q >> 7;
        int r = q & 127;
        Ms[k * 128 + r] = g_m[b][k][s0 + r];
        Mt[k * 128 + r] = g_m[b][k][t0 + r];
    }

    // fp16 accumulators: 2 b32 regs per mma tile (4 f16 values)
    uint32_t acc[4][4][2];
#pragma unroll
    for (int im = 0; im < 4; im++)
#pragma unroll
        for (int in = 0; in < 4; in++) { acc[im][in][0] = 0u; acc[im][in][1] = 0u; }

    const int a_r   = lane & 15;
    const int a_sel = (lane >> 4) << 3;
    const int b_r   = (lane & 7) + ((lane >> 4) << 3);
    const int b_sel = ((lane >> 3) & 1) << 3;

    for (int ck = 0; ck < 4; ck++) {
        if (ck < 3) {
            const int kcn = (ck + 1) * KC;
            const int stn = (ck + 1) & 1;
#pragma unroll
            for (int it = 0; it < 4; it++) {
                int row = lrow + it * 32;
                uint32_t soff = (uint32_t)(stn * STAGE_ELEMS + row * SROW + lch) * 2;
                CP_ASYNC16(as_base + soff, &g_fh[b][s0 + row][kcn + lch]);
                CP_ASYNC16(bs_base + soff, &g_fh[b][t0 + row][kcn + lch]);
            }
            CP_COMMIT();
            CP_WAIT1();
        } else {
            CP_WAIT0();
        }
        __syncthreads();

        const int st = ck & 1;
        __half* Ac = As + st * STAGE_ELEMS;
        __half* Bc = Bs + st * STAGE_ELEMS;

#pragma unroll
        for (int kk = 0; kk < KC; kk += 16) {
            unsigned af[4][4];
#pragma unroll
            for (int im = 0; im < 4; im++) {
                unsigned addr = (unsigned)__cvta_generic_to_shared(
                    &Ac[(wm * 64 + im * 16 + a_r) * SROW + kk + a_sel]);
                asm volatile(
                    "ldmatrix.sync.aligned.m8n8.x4.shared.b16 {%0,%1,%2,%3}, [%4];"
                    : "=r"(af[im][0]), "=r"(af[im][1]), "=r"(af[im][2]), "=r"(af[im][3])
                    : "r"(addr));
            }
            unsigned bq[2][4];
#pragma unroll
            for (int q = 0; q < 2; q++) {
                unsigned addr = (unsigned)__cvta_generic_to_shared(
                    &Bc[(wn * 32 + q * 16 + b_r) * SROW + kk + b_sel]);
                asm volatile(
                    "ldmatrix.sync.aligned.m8n8.x4.shared.b16 {%0,%1,%2,%3}, [%4];"
                    : "=r"(bq[q][0]), "=r"(bq[q][1]), "=r"(bq[q][2]), "=r"(bq[q][3])
                    : "r"(addr));
            }
#pragma unroll
            for (int im = 0; im < 4; im++) {
#pragma unroll
                for (int in = 0; in < 4; in++) {
                    unsigned b0 = bq[in >> 1][(in & 1) * 2];
                    unsigned b1 = bq[in >> 1][(in & 1) * 2 + 1];
                    asm volatile(
                        "mma.sync.aligned.m16n8k16.row.col.f16.f16.f16.f16 "
                        "{%0,%1}, {%2,%3,%4,%5}, {%6,%7}, {%0,%1};"
                        : "+r"(acc[im][in][0]), "+r"(acc[im][in][1])
                        : "r"(af[im][0]), "r"(af[im][1]), "r"(af[im][2]), "r"(af[im][3]),
                          "r"(b0), "r"(b1));
                }
            }
        }
        __syncthreads();
    }

    // fused affinity epilogue
    const int gr = lane >> 2;
    const int gc = (lane & 3) * 2;
    float numL = 0.0f, denL = 0.0f;
#pragma unroll
    for (int im = 0; im < 4; im++) {
#pragma unroll
        for (int in = 0; in < 4; in++) {
#pragma unroll
            for (int r = 0; r < 4; r++) {
                __half2 h2 = *(__half2*)&acc[im][in][r >> 1];
                float v = (r & 1) ? __high2float(h2) : __low2float(h2);
                if (v > SIM_TH) {
                    int row = wm * 64 + im * 16 + gr + ((r >> 1) << 3);
                    int col = wn * 32 + in * 8 + gc + (r & 1);
                    denL += 1.0f;
                    float d = 0.0f;
#pragma unroll
                    for (int k = 0; k < KK; k++)
                        d += fabsf(Ms[k * 128 + row] - Mt[k * 128 + col]);
                    numL += d;
                }
            }
        }
    }
    numL *= w;
    denL *= w;

#pragma unroll
    for (int off = 16; off > 0; off >>= 1) {
        numL += __shfl_xor_sync(0xFFFFFFFFu, numL, off);
        denL += __shfl_xor_sync(0xFFFFFFFFu, denL, off);
    }
    if (lane == 0) { red[wid] = numL; red[8 + wid] = denL; }
    __syncthreads();
    if (tid == 0) {
        float n = 0.0f, d = 0.0f;
#pragma unroll
        for (int q = 0; q < 8; q++) { n += red[q]; d += red[8 + q]; }
        atomicAdd(&g_num, n);
        atomicAdd(&g_den, d);
        __threadfence();
        unsigned t = atomicAdd(&g_done, 1u);
        if (t == GRID2 - 1) {
            out[0] = g_num / (g_den + EPS_DEN);
        }
    }
}

extern "C" void kernel_launch(void* const* d_in, const int* in_sizes, int n_in,
                              void* d_out, int out_size)
{
    const float* masks   = (const float*)d_in[0];
    const float* feats   = (const float*)d_in[1];
    const int*   indices = (const int*)d_in[2];
    float* out = (float*)d_out;

    cudaFuncSetAttribute(gram_affinity_kernel,
                         cudaFuncAttributeMaxDynamicSharedMemorySize, SMEM_BYTES);

    gather_kernel<<<1024, 256>>>(masks, feats, indices);
    gram_affinity_kernel<<<GRID2, 256, SMEM_BYTES>>>(out);
}